// round 10
// baseline (speedup 1.0000x reference)
#include <cuda_runtime.h>
#include <cuda_bf16.h>
#include <cuda_fp8.h>
#include <math.h>
#include <stdint.h>

#define SOSTOK 65
#define G 125

// ---------------- static device scratch ----------------
__device__ uint4 g_W8[2048000];             // W_out fp8 fragment-packed (32.8 MB), scale 64
__device__ uint4 g_WgP[1048576];            // 4096x2048 bf16 packed, gate-interleaved rows
__device__ uint4 g_WcP[262144];             // 1024x2048 bf16 packed
__device__ uint4 g_WihfP[131072];
__device__ uint4 g_WihbP[131072];
__device__ uint4 g_WattnP[32768];           // 128x2048 packed
__device__ uint4 g_EOP[16384];              // EO^T (1024x128) packed fragments
__device__ __nv_bfloat16 g_Whhf_bf[1048576];
__device__ __nv_bfloat16 g_Whhb_bf[1048576];
__device__ __nv_bfloat16 g_E0_bf[65536];
__device__ float g_bg[4096];
__device__ float g_Xf[262144];
__device__ float g_Xb[262144];
__device__ float g_henc[2][2][512];
__device__ float g_cenc[2][512];
__device__ __nv_bfloat16 g_EO_bf[131072];   // [d][t]
__device__ float g_c[32768];
__device__ unsigned char g_h8[32768];       // h fp8, scale 256
__device__ __nv_bfloat16 g_xattn[65536];    // [e | h]
__device__ __nv_bfloat16 g_ctx[32768];      // [b][1024]
__device__ __nv_bfloat16 g_comb[32768];     // [b][1024]
__device__ float g_cE[32768];               // comb_e partial [row][b]
__device__ float g_sc[4096];                // scores [l][b]
__device__ float g_gh[131072];              // Whh@h partial [row][b]
__device__ float g_nll[4096];
__device__ unsigned long long g_ectr;
__device__ unsigned long long g_dctr;
__device__ unsigned long long g_amaxP[G * 32];
__device__ float g_sumP[G * 32];
__device__ float g_tgtL[32];

__device__ __forceinline__ float sigm(float x) { return 1.0f / (1.0f + expf(-x)); }

__device__ __forceinline__ float dot8f(uint4 u, float4 h0, float4 h1) {
    __nv_bfloat162 p0 = *(__nv_bfloat162*)&u.x, p1 = *(__nv_bfloat162*)&u.y;
    __nv_bfloat162 p2 = *(__nv_bfloat162*)&u.z, p3 = *(__nv_bfloat162*)&u.w;
    return __low2float(p0) * h0.x + __high2float(p0) * h0.y
         + __low2float(p1) * h0.z + __high2float(p1) * h0.w
         + __low2float(p2) * h1.x + __high2float(p2) * h1.y
         + __low2float(p3) * h1.z + __high2float(p3) * h1.w;
}

__device__ __forceinline__ unsigned pk2(float a, float b) {
    __nv_bfloat162 t;
    t.x = __float2bfloat16(a);
    t.y = __float2bfloat16(b);
    return *(unsigned*)&t;
}

__device__ __forceinline__ unsigned fp8b(float x) {
    return (unsigned)__nv_cvt_float_to_fp8(x, __NV_SATFINITE, __NV_E4M3);
}

__device__ __forceinline__ unsigned fordu(float f) {
    unsigned u = __float_as_uint(f);
    return u ^ ((u >> 31) ? 0xFFFFFFFFu : 0x80000000u);
}

#define MMA_BF16(acc, a, b0, b1)                                                  \
    asm volatile(                                                                 \
        "mma.sync.aligned.m16n8k16.row.col.f32.bf16.bf16.f32 "                    \
        "{%0,%1,%2,%3}, {%4,%5,%6,%7}, {%8,%9}, {%0,%1,%2,%3};\n"                 \
        : "+f"((acc)[0]), "+f"((acc)[1]), "+f"((acc)[2]), "+f"((acc)[3])          \
        : "r"((a).x), "r"((a).y), "r"((a).z), "r"((a).w), "r"(b0), "r"(b1))

#define MMA_FP8(acc, a, b0, b1)                                                   \
    asm volatile(                                                                 \
        "mma.sync.aligned.m16n8k32.row.col.f32.e4m3.e4m3.f32 "                    \
        "{%0,%1,%2,%3}, {%4,%5,%6,%7}, {%8,%9}, {%0,%1,%2,%3};\n"                 \
        : "+f"((acc)[0]), "+f"((acc)[1]), "+f"((acc)[2]), "+f"((acc)[3])          \
        : "r"((a).x), "r"((a).y), "r"((a).z), "r"((a).w), "r"(b0), "r"(b1))

// ---------------- weight packing ----------------
__device__ __forceinline__ void pack_one(uint4* dst, const float* src, int i, int S, int K) {
    int lane = i & 31;
    int t2 = i >> 5;
    int kc = t2 & ((1 << S) - 1);
    int mt = t2 >> S;
    int r0 = mt * 16 + (lane >> 2);
    int c0 = kc * 16 + (lane & 3) * 2;
    const float* s0 = src + (size_t)r0 * K + c0;
    const float* s8 = s0 + (size_t)8 * K;
    uint4 v;
    v.x = pk2(s0[0], s0[1]);
    v.y = pk2(s8[0], s8[1]);
    v.z = pk2(s0[8], s0[9]);
    v.w = pk2(s8[8], s8[9]);
    dst[i] = v;
}

__device__ __forceinline__ float wg_src(const float* Wih, const float* Whh, int r, int c) {
    int srow = (r & 3) * 1024 + (r >> 2);
    return (c < 1024) ? Wih[(size_t)srow * 1024 + c] : Whh[(size_t)srow * 1024 + c - 1024];
}

__global__ void pack_all(const float* __restrict__ Wout, const float* __restrict__ Wihd,
                         const float* __restrict__ Whhd, const float* __restrict__ Wc,
                         const float* __restrict__ Wihf, const float* __restrict__ Wihb,
                         const float* __restrict__ Wattn) {
    const int S0 = 2048000, S1 = S0 + 1048576, S2 = S1 + 262144,
              S3 = S2 + 131072, S4 = S3 + 131072, S5 = S4 + 32768;
    for (int i = blockIdx.x * blockDim.x + threadIdx.x; i < S5; i += gridDim.x * blockDim.x) {
        if (i < S0) {
            int lane = i & 31;
            int kc = (i >> 5) & 31;
            int mt = i >> 10;
            unsigned w[4];
#pragma unroll
            for (int widx = 0; widx < 4; widx++) {
                int r = mt * 16 + (lane >> 2) + (widx & 1) * 8;
                int c = kc * 32 + (lane & 3) * 4 + (widx >> 1) * 16;
                const float* s = Wout + (size_t)r * 1024 + c;
                w[widx] = fp8b(s[0] * 64.f) | (fp8b(s[1] * 64.f) << 8)
                        | (fp8b(s[2] * 64.f) << 16) | (fp8b(s[3] * 64.f) << 24);
            }
            uint4 v;
            v.x = w[0]; v.y = w[1]; v.z = w[2]; v.w = w[3];
            g_W8[i] = v;
        }
        else if (i < S1) {
            int r = i - S0;
            int lane = r & 31;
            int t2 = r >> 5;
            int kc = t2 & 127;
            int mt = t2 >> 7;
            int r0 = mt * 16 + (lane >> 2);
            int c0 = kc * 16 + (lane & 3) * 2;
            uint4 v;
            v.x = pk2(wg_src(Wihd, Whhd, r0, c0), wg_src(Wihd, Whhd, r0, c0 + 1));
            v.y = pk2(wg_src(Wihd, Whhd, r0 + 8, c0), wg_src(Wihd, Whhd, r0 + 8, c0 + 1));
            v.z = pk2(wg_src(Wihd, Whhd, r0, c0 + 8), wg_src(Wihd, Whhd, r0, c0 + 9));
            v.w = pk2(wg_src(Wihd, Whhd, r0 + 8, c0 + 8), wg_src(Wihd, Whhd, r0 + 8, c0 + 9));
            g_WgP[r] = v;
        }
        else if (i < S2) pack_one(g_WcP, Wc, i - S1, 7, 2048);
        else if (i < S3) pack_one(g_WihfP, Wihf, i - S2, 5, 512);
        else if (i < S4) pack_one(g_WihbP, Wihb, i - S3, 5, 512);
        else pack_one(g_WattnP, Wattn, i - S4, 7, 2048);
    }
}

// ---------------- misc conversion + init ----------------
__global__ void conv_misc(const float* __restrict__ Whhf, const float* __restrict__ Whhb,
                          const float* __restrict__ emb_enc, const int* __restrict__ x,
                          const float* __restrict__ bihd, const float* __restrict__ bhhd) {
    const int A0 = 1048576, A1 = 2097152, A2 = 2162688, A3 = 2166784,
              A4 = 2199552, A5 = 2330624;
    for (int i = blockIdx.x * blockDim.x + threadIdx.x; i < A5; i += gridDim.x * blockDim.x) {
        if (i < A0) g_Whhf_bf[i] = __float2bfloat16(Whhf[i]);
        else if (i < A1) g_Whhb_bf[i - A0] = __float2bfloat16(Whhb[i - A0]);
        else if (i < A2) {
            int r = i - A1;
            int tt = r >> 9, k = r & 511;
            g_E0_bf[r] = __float2bfloat16(emb_enc[(size_t)x[tt] * 512 + k]);
        } else if (i < A3) {
            int r = i - A2;
            int srow = (r & 3) * 1024 + (r >> 2);
            g_bg[r] = bihd[srow] + bhhd[srow];
        } else if (i < A4) {
            int r = i - A3;
            g_c[r] = 0.f;
            int b = r >> 10, j = r & 1023;
            g_xattn[b * 2048 + 1024 + j] = __float2bfloat16(0.f);
            if (r < 2048) ((float*)g_henc)[r] = 0.f;
            if (r < 1024) ((float*)g_cenc)[r] = 0.f;
        } else {
            g_gh[i - A4] = 0.f;
        }
    }
}

// ---------------- packed-A GEMM (encoder precompute) ------
template <int KC, int NT>
__global__ __launch_bounds__(128) void gemm_packed(
    const uint4* __restrict__ Ap, const __nv_bfloat16* __restrict__ X, int xld,
    const float* __restrict__ bias, const float* __restrict__ bias2,
    float* __restrict__ outF, int ofld)
{
    int w = (blockIdx.x * blockDim.x + threadIdx.x) >> 5;
    int lane = threadIdx.x & 31;
    int gr = lane >> 2;
    int gc = (lane & 3) * 2;
    float acc[NT][4];
#pragma unroll
    for (int a = 0; a < NT; a++)
#pragma unroll
        for (int q = 0; q < 4; q++) acc[a][q] = 0.f;

    const uint4* ap = Ap + (size_t)w * KC * 32 + lane;
#pragma unroll 8
    for (int kc = 0; kc < KC; kc++) {
        uint4 a = ap[(size_t)kc * 32];
#pragma unroll
        for (int nt = 0; nt < NT; nt++) {
            const __nv_bfloat16* xb = X + (size_t)(nt * 8 + gr) * xld + gc + kc * 16;
            unsigned b0 = *(const unsigned*)xb;
            unsigned b1 = *(const unsigned*)(xb + 8);
            MMA_BF16(acc[nt], a, b0, b1);
        }
    }
    int mA = w * 16 + gr, mB = mA + 8;
    float bA = bias[mA] + bias2[mA];
    float bB = bias[mB] + bias2[mB];
#pragma unroll
    for (int nt = 0; nt < NT; nt++) {
        int n0 = nt * 8 + gc;
        outF[(size_t)n0 * ofld + mA] = acc[nt][0] + bA;
        outF[(size_t)(n0 + 1) * ofld + mA] = acc[nt][1] + bA;
        outF[(size_t)n0 * ofld + mB] = acc[nt][2] + bB;
        outF[(size_t)(n0 + 1) * ofld + mB] = acc[nt][3] + bB;
    }
}

// ---------------- persistent encoder ----------------
__global__ __launch_bounds__(256) void enc_persist() {
    __shared__ float sg[32];
    int dir = blockIdx.x >> 6, jb = blockIdx.x & 63, tid = threadIdx.x;
    int rl = tid >> 3, part = tid & 7;
    int q = rl >> 3, jl = rl & 7;
    int row = q * 512 + jb * 8 + jl;
    const uint4* Wr = (const uint4*)((dir ? g_Whhb_bf : g_Whhf_bf) + (size_t)row * 512 + part * 64);
    const float* Xr = dir ? g_Xb : g_Xf;
    for (int t = 0; t < 128; t++) {
        const float4* hp = (const float4*)(g_henc[t & 1][dir] + part * 64);
        float acc = 0.f;
#pragma unroll
        for (int k = 0; k < 8; k++) {
            float4 h0 = __ldcg(hp + 2 * k);
            float4 h1 = __ldcg(hp + 2 * k + 1);
            acc += dot8f(Wr[k], h0, h1);
        }
        acc += __shfl_xor_sync(0xffffffffu, acc, 1);
        acc += __shfl_xor_sync(0xffffffffu, acc, 2);
        acc += __shfl_xor_sync(0xffffffffu, acc, 4);
        if (part == 0) sg[rl] = acc + Xr[t * 2048 + row];
        __syncthreads();
        if (tid < 8) {
            int j = jb * 8 + tid;
            float iv = sg[tid], fv = sg[8 + tid], gv = sg[16 + tid], ov = sg[24 + tid];
            float c = g_cenc[dir][j];
            c = sigm(fv) * c + sigm(iv) * tanhf(gv);
            float h = sigm(ov) * tanhf(c);
            g_cenc[dir][j] = c;
            g_henc[(t + 1) & 1][dir][j] = h;
            g_EO_bf[(dir * 512 + j) * 128 + t] = __float2bfloat16(h);
        }
        __syncthreads();
        if (tid == 0) {
            __threadfence();
            unsigned long long old = atomicAdd(&g_ectr, 1ull);
            unsigned long long tv = ((old >> 7) << 7) + 128ull;
            unsigned long long v;
            do {
                asm volatile("ld.global.cg.u64 %0, [%1];" : "=l"(v) : "l"(&g_ectr));
            } while (v < tv);
            __threadfence();
        }
        __syncthreads();
    }
}

// ---------------- persistent decoder ----------------
__device__ __forceinline__ void gbar() {
    __syncthreads();
    if (threadIdx.x == 0) {
        __threadfence();
        unsigned long long old = atomicAdd(&g_dctr, 1ull);
        unsigned long long tv = (old / G) * G + G;
        unsigned long long v;
        do {
            asm volatile("ld.global.cg.u64 %0, [%1];" : "=l"(v) : "l"(&g_dctr));
        } while (v < tv);
        __threadfence();
    }
    __syncthreads();
}

__device__ __forceinline__ unsigned ldcg_u(const __nv_bfloat16* p) {
    return __ldcg((const unsigned*)p);
}

__global__ __launch_bounds__(256) void dec_persist(
    const float* __restrict__ emb_dec, const float* __restrict__ battn,
    const float* __restrict__ bcomb, const float* __restrict__ bout,
    const int* __restrict__ tgt)
{
    extern __shared__ __align__(16) char dsm[];
    int bid = blockIdx.x, tid = threadIdx.x;
    int wl = tid >> 5, lane = tid & 31;
    int gr = lane >> 2, gc = (lane & 3) * 2, tc = lane & 3;

    // pre-phase: pack EO fragments
    for (int i = bid * 256 + tid; i < 16384; i += G * 256) {
        int lane2 = i & 31, kc = (i >> 5) & 7, mt = i >> 8;
        int r0 = mt * 16 + (lane2 >> 2);
        int c0 = kc * 16 + (lane2 & 3) * 2;
        uint4 v;
        v.x = *(const unsigned*)(g_EO_bf + (size_t)r0 * 128 + c0);
        v.y = *(const unsigned*)(g_EO_bf + (size_t)(r0 + 8) * 128 + c0);
        v.z = *(const unsigned*)(g_EO_bf + (size_t)r0 * 128 + c0 + 8);
        v.w = *(const unsigned*)(g_EO_bf + (size_t)(r0 + 8) * 128 + c0 + 8);
        g_EOP[i] = v;
    }
    gbar();

    for (int t = 0; t <= 128; t++) {
        // ======== Phase A: token resolve + embed (blocks 0..31) ========
        if (bid < 32) {
            int b = bid;
            int tok = SOSTOK;
            if (t > 0) {
                unsigned long long* rk = (unsigned long long*)dsm;
                float* rs = (float*)(dsm + 1024);
                unsigned long long k = 0;
                float s = 0.f;
                if (tid < G) {
                    k = __ldcg(&g_amaxP[tid * 32 + b]);
                    s = __ldcg(&g_sumP[tid * 32 + b]);
                }
                if (tid < 128) { rk[tid] = k; rs[tid] = s; }
                __syncthreads();
                for (int off = 64; off; off >>= 1) {
                    if (tid < off) {
                        if (rk[tid + off] > rk[tid]) rk[tid] = rk[tid + off];
                        rs[tid] += rs[tid + off];
                    }
                    __syncthreads();
                }
                tok = (int)(0xFFFFFFFFu - (unsigned)(rk[0] & 0xFFFFFFFFull));
                if (tid == 0) {
                    float lse = logf(rs[0]);
                    float tl = __ldcg(&g_tgtL[b]);
                    g_nll[(t - 1) * 32 + b] = -(tl - lse);
                }
            }
            if (t < 128) {
                const float4* er = (const float4*)(emb_dec + (size_t)tok * 1024);
                float4 v = er[tid];
                unsigned* xa = (unsigned*)(g_xattn + b * 2048 + tid * 4);
                xa[0] = pk2(v.x, v.y);
                xa[1] = pk2(v.z, v.w);
            }
        }
        gbar();
        if (t == 128) break;

        // ======== Phase B: comb_e (blocks 0..63) + scores (64..71) ========
        if (bid < 64) {
            float (*part)[16][33] = (float (*)[16][33])dsm;
            float acc[4][4];
#pragma unroll
            for (int a = 0; a < 4; a++)
#pragma unroll
                for (int q2 = 0; q2 < 4; q2++) acc[a][q2] = 0.f;
            int kc0 = wl * 8;
#pragma unroll
            for (int kk = 0; kk < 8; kk++) {
                int kc = kc0 + kk;
                uint4 a = g_WcP[(size_t)bid * 4096 + kc * 32 + lane];
#pragma unroll
                for (int nt = 0; nt < 4; nt++) {
                    int row = nt * 8 + gr;
                    unsigned b0 = ldcg_u(g_xattn + row * 2048 + kc * 16 + gc);
                    unsigned b1 = ldcg_u(g_xattn + row * 2048 + kc * 16 + gc + 8);
                    MMA_BF16(acc[nt], a, b0, b1);
                }
            }
#pragma unroll
            for (int nt = 0; nt < 4; nt++) {
                int n0 = nt * 8 + gc;
                part[wl][gr][n0] = acc[nt][0];
                part[wl][gr][n0 + 1] = acc[nt][1];
                part[wl][gr + 8][n0] = acc[nt][2];
                part[wl][gr + 8][n0 + 1] = acc[nt][3];
            }
            __syncthreads();
#pragma unroll
            for (int it = 0; it < 2; it++) {
                int idx = tid + it * 256;
                int rr = idx >> 5, b = idx & 31;
                float s = 0.f;
#pragma unroll
                for (int w2 = 0; w2 < 8; w2++) s += part[w2][rr][b];
                g_cE[(bid * 16 + rr) * 32 + b] = s;
            }
        } else if (bid < 72) {
            int tile = bid - 64;
            float (*part)[16][33] = (float (*)[16][33])dsm;
            float acc[4][4];
#pragma unroll
            for (int a = 0; a < 4; a++)
#pragma unroll
                for (int q2 = 0; q2 < 4; q2++) acc[a][q2] = 0.f;
            int kc0 = wl * 16;
#pragma unroll
            for (int kk = 0; kk < 16; kk++) {
                int kc = kc0 + kk;
                uint4 a = g_WattnP[(size_t)tile * 4096 + kc * 32 + lane];
#pragma unroll
                for (int nt = 0; nt < 4; nt++) {
                    int row = nt * 8 + gr;
                    unsigned b0 = ldcg_u(g_xattn + row * 2048 + kc * 16 + gc);
                    unsigned b1 = ldcg_u(g_xattn + row * 2048 + kc * 16 + gc + 8);
                    MMA_BF16(acc[nt], a, b0, b1);
                }
            }
#pragma unroll
            for (int nt = 0; nt < 4; nt++) {
                int n0 = nt * 8 + gc;
                part[wl][gr][n0] = acc[nt][0];
                part[wl][gr][n0 + 1] = acc[nt][1];
                part[wl][gr + 8][n0] = acc[nt][2];
                part[wl][gr + 8][n0 + 1] = acc[nt][3];
            }
            __syncthreads();
#pragma unroll
            for (int it = 0; it < 2; it++) {
                int idx = tid + it * 256;
                int rr = idx >> 5, b = idx & 31;
                float s = battn[tile * 16 + rr];
#pragma unroll
                for (int w2 = 0; w2 < 8; w2++) s += part[w2][rr][b];
                g_sc[(tile * 16 + rr) * 32 + b] = s;
            }
        }
        gbar();

        // ======== Phase C: softmax + ctx (blocks 0..31) ========
        if (bid < 32) {
            __nv_bfloat16 (*saw)[136] = (__nv_bfloat16 (*)[136])dsm;
#pragma unroll
            for (int i = 0; i < 4; i++) {
                int b = wl * 4 + i;
                float v0 = __ldcg(&g_sc[lane * 32 + b]);
                float v1 = __ldcg(&g_sc[(lane + 32) * 32 + b]);
                float v2 = __ldcg(&g_sc[(lane + 64) * 32 + b]);
                float v3 = __ldcg(&g_sc[(lane + 96) * 32 + b]);
                float mx = fmaxf(fmaxf(v0, v1), fmaxf(v2, v3));
#pragma unroll
                for (int o = 16; o; o >>= 1) mx = fmaxf(mx, __shfl_xor_sync(0xffffffffu, mx, o));
                float e0 = expf(v0 - mx), e1 = expf(v1 - mx), e2 = expf(v2 - mx), e3 = expf(v3 - mx);
                float s = e0 + e1 + e2 + e3;
#pragma unroll
                for (int o = 16; o; o >>= 1) s += __shfl_xor_sync(0xffffffffu, s, o);
                float inv = 1.f / s;
                saw[b][lane] = __float2bfloat16(e0 * inv);
                saw[b][lane + 32] = __float2bfloat16(e1 * inv);
                saw[b][lane + 64] = __float2bfloat16(e2 * inv);
                saw[b][lane + 96] = __float2bfloat16(e3 * inv);
            }
            __syncthreads();
            if (wl < 2) {
                int tile = bid * 2 + wl;
                float acc[4][4];
#pragma unroll
                for (int a = 0; a < 4; a++)
#pragma unroll
                    for (int q2 = 0; q2 < 4; q2++) acc[a][q2] = 0.f;
#pragma unroll
                for (int kc = 0; kc < 8; kc++) {
                    uint4 a = g_EOP[((size_t)tile * 8 + kc) * 32 + lane];
#pragma unroll
                    for (int nt = 0; nt < 4; nt++) {
                        unsigned b0 = *(const unsigned*)&saw[nt * 8 + gr][kc * 16 + gc];
                        unsigned b1 = *(const unsigned*)&saw[nt * 8 + gr][kc * 16 + gc + 8];
                        MMA_BF16(acc[nt], a, b0, b1);
                    }
                }
                int dA = tile * 16 + gr, dB = dA + 8;
#pragma unroll
                for (int nt = 0; nt < 4; nt++) {
                    int n0 = nt * 8 + gc;
                    g_ctx[n0 * 1024 + dA] = __float2bfloat16(acc[nt][0]);
                    g_ctx[(n0 + 1) * 1024 + dA] = __float2bfloat16(acc[nt][1]);
                    g_ctx[n0 * 1024 + dB] = __float2bfloat16(acc[nt][2]);
                    g_ctx[(n0 + 1) * 1024 + dB] = __float2bfloat16(acc[nt][3]);
                }
            }
        }
        gbar();

        // ======== Phase D: comb_ctx + finalize comb (blocks 0..31) ========
        if (bid < 32) {
            float (*part)[4][16][33] = (float (*)[4][16][33])dsm;
            int tt = wl >> 2, q4 = wl & 3;
            int tile = bid * 2 + tt;
            float acc[4][4];
#pragma unroll
            for (int a = 0; a < 4; a++)
#pragma unroll
                for (int q2 = 0; q2 < 4; q2++) acc[a][q2] = 0.f;
            int kc0 = 64 + q4 * 16;
#pragma unroll
            for (int kk = 0; kk < 16; kk++) {
                int kc = kc0 + kk;
                uint4 a = g_WcP[(size_t)tile * 4096 + kc * 32 + lane];
                int col = (kc - 64) * 16 + gc;
#pragma unroll
                for (int nt = 0; nt < 4; nt++) {
                    int row = nt * 8 + gr;
                    unsigned b0 = ldcg_u(g_ctx + row * 1024 + col);
                    unsigned b1 = ldcg_u(g_ctx + row * 1024 + col + 8);
                    MMA_BF16(acc[nt], a, b0, b1);
                }
            }
#pragma unroll
            for (int nt = 0; nt < 4; nt++) {
                int n0 = nt * 8 + gc;
                part[tt][q4][gr][n0] = acc[nt][0];
                part[tt][q4][gr][n0 + 1] = acc[nt][1];
                part[tt][q4][gr + 8][n0] = acc[nt][2];
                part[tt][q4][gr + 8][n0 + 1] = acc[nt][3];
            }
            __syncthreads();
#pragma unroll
            for (int it = 0; it < 4; it++) {
                int idx = tid + it * 256;
                int t2 = idx >> 9, rr = (idx >> 5) & 15, b = idx & 31;
                int row = (bid * 2 + t2) * 16 + rr;
                float s = __ldcg(&g_cE[row * 32 + b]) + bcomb[row];
#pragma unroll
                for (int q2 = 0; q2 < 4; q2++) s += part[t2][q2][rr][b];
                g_comb[b * 1024 + row] = __float2bfloat16(fmaxf(s, 0.f));
            }
        }
        gbar();

        // ======== Phase E: gates_comb + gh + cell (blocks 0..63) ========
        if (bid < 64) {
            float (*part)[2][16][33] = (float (*)[2][16][33])dsm;
            int tl = wl >> 1, half = wl & 1;
            int tile = bid * 4 + tl;
            float acc[4][4];
#pragma unroll
            for (int a = 0; a < 4; a++)
#pragma unroll
                for (int q2 = 0; q2 < 4; q2++) acc[a][q2] = 0.f;
            int kc0 = half * 32;
#pragma unroll 8
            for (int kk = 0; kk < 32; kk++) {
                int kc = kc0 + kk;
                uint4 a = g_WgP[(size_t)tile * 4096 + kc * 32 + lane];
                int col = kc * 16 + gc;
#pragma unroll
                for (int nt = 0; nt < 4; nt++) {
                    int row = nt * 8 + gr;
                    unsigned b0 = ldcg_u(g_comb + row * 1024 + col);
                    unsigned b1 = ldcg_u(g_comb + row * 1024 + col + 8);
                    MMA_BF16(acc[nt], a, b0, b1);
                }
            }
#pragma unroll
            for (int nt = 0; nt < 4; nt++) {
                int n0 = nt * 8 + gc;
                part[tl][half][gr][n0] = acc[nt][0];
                part[tl][half][gr][n0 + 1] = acc[nt][1];
                part[tl][half][gr + 8][n0] = acc[nt][2];
                part[tl][half][gr + 8][n0 + 1] = acc[nt][3];
            }
            __syncthreads();
#pragma unroll
            for (int it = 0; it < 2; it++) {
                int idx = tid + it * 256;
                int jl = idx >> 5, b = idx & 31;
                float gt[4];
#pragma unroll
                for (int q2 = 0; q2 < 4; q2++) {
                    int lr = jl * 4 + q2;
                    int grow = bid * 64 + lr;
                    gt[q2] = part[lr >> 4][0][lr & 15][b] + part[lr >> 4][1][lr & 15][b]
                           + g_bg[grow] + g_gh[grow * 32 + b];
                }
                int jg = bid * 16 + jl;
                float c = g_c[b * 1024 + jg];
                c = sigm(gt[1]) * c + sigm(gt[0]) * tanhf(gt[2]);
                float h = sigm(gt[3]) * tanhf(c);
                g_c[b * 1024 + jg] = c;
                g_xattn[b * 2048 + 1024 + jg] = __float2bfloat16(h);
                g_h8[b * 1024 + jg] = (unsigned char)fp8b(h * 256.f);
            }
        }
        gbar();

        // ======== Phase F: fp8 logits + partials + gates_h(t+1) ========
        {
            unsigned char (*sx8)[1040] = (unsigned char (*)[1040])dsm;
            int tile0 = (bid * 8 + wl) * 2;
            for (int i = tid; i < 2048; i += 256) {
                int r = i >> 6, c2 = i & 63;
                *(uint4*)&sx8[r][c2 * 16] = __ldcg((const uint4*)(g_h8 + r * 1024 + c2 * 16));
            }
            __syncthreads();
            float acc[2][4][4];
#pragma unroll
            for (int m = 0; m < 2; m++)
#pragma unroll
                for (int a = 0; a < 4; a++)
#pragma unroll
                    for (int q2 = 0; q2 < 4; q2++) acc[m][a][q2] = 0.f;
#pragma unroll 4
            for (int kc = 0; kc < 32; kc++) {
                uint4 a0 = g_W8[((size_t)tile0 * 32 + kc) * 32 + lane];
                uint4 a1 = g_W8[((size_t)(tile0 + 1) * 32 + kc) * 32 + lane];
#pragma unroll
                for (int nt = 0; nt < 4; nt++) {
                    unsigned b0 = *(const unsigned*)&sx8[nt * 8 + gr][kc * 32 + 4 * tc];
                    unsigned b1 = *(const unsigned*)&sx8[nt * 8 + gr][kc * 32 + 4 * tc + 16];
                    MMA_FP8(acc[0][nt], a0, b0, b1);
                    MMA_FP8(acc[1][nt], a1, b0, b1);
                }
            }
            __syncthreads();
            float* sL = (float*)dsm;
            const float sc8 = 1.f / 16384.f;
#pragma unroll
            for (int m = 0; m < 2; m++) {
                int rA = (wl * 2 + m) * 16 + gr, rB = rA + 8;
                float bA = bout[bid * 256 + rA], bB = bout[bid * 256 + rB];
#pragma unroll
                for (int nt = 0; nt < 4; nt++) {
                    int n0 = nt * 8 + gc;
                    sL[rA * 33 + n0] = acc[m][nt][0] * sc8 + bA;
                    sL[rA * 33 + n0 + 1] = acc[m][nt][1] * sc8 + bA;
                    sL[rB * 33 + n0] = acc[m][nt][2] * sc8 + bB;
                    sL[rB * 33 + n0 + 1] = acc[m][nt][3] * sc8 + bB;
                }
            }
            __syncthreads();
            unsigned long long* pkey = (unsigned long long*)(dsm + 34816);
            float* psum = (float*)(dsm + 36864);
            int b2 = tid & 31, seg = tid >> 5;
            unsigned long long bk = 0;
            float sm = 0.f;
#pragma unroll 4
            for (int r0 = 0; r0 < 32; r0++) {
                int r = seg * 32 + r0;
                float f = sL[r * 33 + b2];
                unsigned long long key = ((unsigned long long)fordu(f) << 32)
                                       | (unsigned long long)(0xFFFFFFFFu - (unsigned)(bid * 256 + r));
                if (key > bk) bk = key;
                sm += expf(f);
            }
            pkey[tid] = bk;
            psum[tid] = sm;
            __syncthreads();
            if (seg == 0) {
#pragma unroll
                for (int s2 = 1; s2 < 8; s2++) {
                    unsigned long long k2 = pkey[s2 * 32 + b2];
                    if (k2 > bk) bk = k2;
                    sm += psum[s2 * 32 + b2];
                }
                g_amaxP[bid * 32 + b2] = bk;
                g_sumP[bid * 32 + b2] = sm;
            }
            if (tid < 32) {
                int tr = tgt[tid * 128 + t];
                if ((tr >> 8) == bid) g_tgtL[tid] = sL[(tr & 255) * 33 + tid];
            }
            __syncthreads();
            // gates_h for next step (blocks 0..63), h just written this step
            if (bid < 64) {
                float (*part)[2][16][33] = (float (*)[2][16][33])dsm;
                int tl = wl >> 1, half = wl & 1;
                int tile = bid * 4 + tl;
                float a2[4][4];
#pragma unroll
                for (int a = 0; a < 4; a++)
#pragma unroll
                    for (int q2 = 0; q2 < 4; q2++) a2[a][q2] = 0.f;
                int kc0 = 64 + half * 32;
#pragma unroll 8
                for (int kk = 0; kk < 32; kk++) {
                    int kc = kc0 + kk;
                    uint4 a = g_WgP[(size_t)tile * 4096 + kc * 32 + lane];
                    int col = (kc - 64) * 16 + gc;
#pragma unroll
                    for (int nt = 0; nt < 4; nt++) {
                        int row = nt * 8 + gr;
                        unsigned b0 = ldcg_u(g_xattn + row * 2048 + 1024 + col);
                        unsigned b1 = ldcg_u(g_xattn + row * 2048 + 1024 + col + 8);
                        MMA_BF16(a2[nt], a, b0, b1);
                    }
                }
#pragma unroll
                for (int nt = 0; nt < 4; nt++) {
                    int n0 = nt * 8 + gc;
                    part[tl][half][gr][n0] = a2[nt][0];
                    part[tl][half][gr][n0 + 1] = a2[nt][1];
                    part[tl][half][gr + 8][n0] = a2[nt][2];
                    part[tl][half][gr + 8][n0 + 1] = a2[nt][3];
                }
                __syncthreads();
#pragma unroll
                for (int it = 0; it < 2; it++) {
                    int idx = tid + it * 256;
                    int lr = idx >> 5, b = idx & 31;
                    // lr 0..15 then 16..31? idx up to 511: lr 0..15 (two iters cover 512 = 16x32)
                    // need 64 rows: loop 4 iterations instead
                }
#pragma unroll
                for (int it = 0; it < 8; it++) {
                    int idx = tid + it * 256;
                    if (idx < 2048) {
                        int lr = idx >> 5, b = idx & 31;  // lr 0..63
                        float s = part[lr >> 4][0][lr & 15][b] + part[lr >> 4][1][lr & 15][b];
                        g_gh[(bid * 64 + lr) * 32 + b] = s;
                    }
                }
            }
        }
        gbar();
    }
}

__global__ void finalize_kernel(float* __restrict__ out) {
    int b = threadIdx.x;  // 32
    float s = 0.f;
    for (int t = 0; t < 128; t++) s += g_nll[t * 32 + b];
    for (int o = 16; o > 0; o >>= 1) s += __shfl_down_sync(0xffffffffu, s, o);
    if (b == 0) {
        float loss = s / 32.0f;
        out[0] = loss;
        out[1] = loss / 128.0f;
    }
}

// ---------------- host launcher ----------------
extern "C" void kernel_launch(void* const* d_in, const int* in_sizes, int n_in,
                              void* d_out, int out_size) {
    const int* x = (const int*)d_in[0];
    const int* tgt = (const int*)d_in[1];
    const float* emb_enc = (const float*)d_in[4];
    const float* Wihf = (const float*)d_in[5];
    const float* Whhf = (const float*)d_in[6];
    const float* bihf = (const float*)d_in[7];
    const float* bhhf = (const float*)d_in[8];
    const float* Wihb = (const float*)d_in[9];
    const float* Whhb = (const float*)d_in[10];
    const float* bihb = (const float*)d_in[11];
    const float* bhhb = (const float*)d_in[12];
    const float* emb_dec = (const float*)d_in[13];
    const float* Wattn = (const float*)d_in[14];
    const float* battn = (const float*)d_in[15];
    const float* Wc = (const float*)d_in[16];
    const float* bcomb = (const float*)d_in[17];
    const float* Wihd = (const float*)d_in[18];
    const float* Whhd = (const float*)d_in[19];
    const float* bihd = (const float*)d_in[20];
    const float* bhhd = (const float*)d_in[21];
    const float* Wout = (const float*)d_in[22];
    const float* bout = (const float*)d_in[23];

    uint4 *pWihfP, *pWihbP;
    __nv_bfloat16* pE0;
    float *pXf, *pXb;
    cudaGetSymbolAddress((void**)&pWihfP, g_WihfP);
    cudaGetSymbolAddress((void**)&pWihbP, g_WihbP);
    cudaGetSymbolAddress((void**)&pE0, g_E0_bf);
    cudaGetSymbolAddress((void**)&pXf, g_Xf);
    cudaGetSymbolAddress((void**)&pXb, g_Xb);

    cudaFuncSetAttribute(dec_persist, cudaFuncAttributeMaxDynamicSharedMemorySize, 59392);

    pack_all<<<2048, 256>>>(Wout, Wihd, Whhd, Wc, Wihf, Wihb, Wattn);
    conv_misc<<<1024, 256>>>(Whhf, Whhb, emb_enc, x, bihd, bhhd);
    gemm_packed<32, 16><<<32, 128>>>(pWihfP, pE0, 512, bihf, bhhf, pXf, 2048);
    gemm_packed<32, 16><<<32, 128>>>(pWihbP, pE0, 512, bihb, bhhb, pXb, 2048);
    enc_persist<<<128, 256>>>();
    dec_persist<<<G, 256, 59392>>>(emb_dec, battn, bcomb, bout, tgt);
    finalize_kernel<<<1, 32>>>((float*)d_out);
}

// round 11
// speedup vs baseline: 2.6183x; 2.6183x over previous
#include <cuda_runtime.h>
#include <cuda_bf16.h>
#include <cuda_fp8.h>
#include <math.h>
#include <stdint.h>

#define SOSTOK 65
#define G 125

// ---------------- static device scratch ----------------
__device__ uint4 g_W8[2048000];             // W_out fp8 fragment-packed (32.8 MB), scale 64
__device__ uint4 g_WgP[1048576];            // 4096x2048 bf16 packed, gate-interleaved rows
__device__ uint4 g_WcP[262144];             // 1024x2048 bf16 packed
__device__ uint4 g_WihfP[131072];
__device__ uint4 g_WihbP[131072];
__device__ uint4 g_WattnP[32768];           // 128x2048 packed
__device__ uint4 g_MP[16384];               // M (1024x128) packed fragments
__device__ float g_Mf[131072];              // M fp32
__device__ __nv_bfloat16 g_EOm[131072];     // enc outputs [t][1024]
__device__ __nv_bfloat16 g_Whhf_bf[1048576];
__device__ __nv_bfloat16 g_Whhb_bf[1048576];
__device__ __nv_bfloat16 g_E0_bf[65536];
__device__ float g_bg[4096];
__device__ float g_Xf[262144];
__device__ float g_Xb[262144];
__device__ float g_henc[2][2][512];
__device__ float g_cenc[2][512];
__device__ float g_c[32768];
__device__ unsigned char g_h8[32768];       // h fp8, scale 256
__device__ __nv_bfloat16 g_xattn[65536];    // [e | h]  [b][2048]
__device__ __nv_bfloat16 g_comb[32768];     // [b][1024]
__device__ float g_cE[32768];               // comb_e partial [row][b]
__device__ float g_sc[4096];                // scores [l][b]
__device__ float g_gh[131072];              // Whh@h partial [grow][b]
__device__ float g_nll[4096];
__device__ unsigned long long g_ectr;
__device__ unsigned long long g_dctr;
__device__ unsigned long long g_amaxP[G * 32];
__device__ float g_sumP[G * 32];
__device__ float g_tgtL[32];

__device__ __forceinline__ float sigm(float x) { return 1.0f / (1.0f + expf(-x)); }

__device__ __forceinline__ float dot8f(uint4 u, float4 h0, float4 h1) {
    __nv_bfloat162 p0 = *(__nv_bfloat162*)&u.x, p1 = *(__nv_bfloat162*)&u.y;
    __nv_bfloat162 p2 = *(__nv_bfloat162*)&u.z, p3 = *(__nv_bfloat162*)&u.w;
    return __low2float(p0) * h0.x + __high2float(p0) * h0.y
         + __low2float(p1) * h0.z + __high2float(p1) * h0.w
         + __low2float(p2) * h1.x + __high2float(p2) * h1.y
         + __low2float(p3) * h1.z + __high2float(p3) * h1.w;
}

__device__ __forceinline__ unsigned pk2(float a, float b) {
    __nv_bfloat162 t;
    t.x = __float2bfloat16(a);
    t.y = __float2bfloat16(b);
    return *(unsigned*)&t;
}

__device__ __forceinline__ unsigned fp8b(float x) {
    return (unsigned)__nv_cvt_float_to_fp8(x, __NV_SATFINITE, __NV_E4M3);
}

__device__ __forceinline__ unsigned fordu(float f) {
    unsigned u = __float_as_uint(f);
    return u ^ ((u >> 31) ? 0xFFFFFFFFu : 0x80000000u);
}

#define MMA_BF16(acc, a, b0, b1)                                                  \
    asm volatile(                                                                 \
        "mma.sync.aligned.m16n8k16.row.col.f32.bf16.bf16.f32 "                    \
        "{%0,%1,%2,%3}, {%4,%5,%6,%7}, {%8,%9}, {%0,%1,%2,%3};\n"                 \
        : "+f"((acc)[0]), "+f"((acc)[1]), "+f"((acc)[2]), "+f"((acc)[3])          \
        : "r"((a).x), "r"((a).y), "r"((a).z), "r"((a).w), "r"(b0), "r"(b1))

#define MMA_FP8(acc, a, b0, b1)                                                   \
    asm volatile(                                                                 \
        "mma.sync.aligned.m16n8k32.row.col.f32.e4m3.e4m3.f32 "                    \
        "{%0,%1,%2,%3}, {%4,%5,%6,%7}, {%8,%9}, {%0,%1,%2,%3};\n"                 \
        : "+f"((acc)[0]), "+f"((acc)[1]), "+f"((acc)[2]), "+f"((acc)[3])          \
        : "r"((a).x), "r"((a).y), "r"((a).z), "r"((a).w), "r"(b0), "r"(b1))

// ---------------- weight packing ----------------
__device__ __forceinline__ void pack_one(uint4* dst, const float* src, int i, int S, int K) {
    int lane = i & 31;
    int t2 = i >> 5;
    int kc = t2 & ((1 << S) - 1);
    int mt = t2 >> S;
    int r0 = mt * 16 + (lane >> 2);
    int c0 = kc * 16 + (lane & 3) * 2;
    const float* s0 = src + (size_t)r0 * K + c0;
    const float* s8 = s0 + (size_t)8 * K;
    uint4 v;
    v.x = pk2(s0[0], s0[1]);
    v.y = pk2(s8[0], s8[1]);
    v.z = pk2(s0[8], s0[9]);
    v.w = pk2(s8[8], s8[9]);
    dst[i] = v;
}

__device__ __forceinline__ float wg_src(const float* Wih, const float* Whh, int r, int c) {
    int srow = (r & 3) * 1024 + (r >> 2);
    return (c < 1024) ? Wih[(size_t)srow * 1024 + c] : Whh[(size_t)srow * 1024 + c - 1024];
}

__global__ void pack_all(const float* __restrict__ Wout, const float* __restrict__ Wihd,
                         const float* __restrict__ Whhd, const float* __restrict__ Wc,
                         const float* __restrict__ Wihf, const float* __restrict__ Wihb,
                         const float* __restrict__ Wattn) {
    const int S0 = 2048000, S1 = S0 + 1048576, S2 = S1 + 262144,
              S3 = S2 + 131072, S4 = S3 + 131072, S5 = S4 + 32768;
    for (int i = blockIdx.x * blockDim.x + threadIdx.x; i < S5; i += gridDim.x * blockDim.x) {
        if (i < S0) {
            int lane = i & 31;
            int kc = (i >> 5) & 31;
            int mt = i >> 10;
            unsigned w[4];
#pragma unroll
            for (int widx = 0; widx < 4; widx++) {
                int r = mt * 16 + (lane >> 2) + (widx & 1) * 8;
                int c = kc * 32 + (lane & 3) * 4 + (widx >> 1) * 16;
                const float* s = Wout + (size_t)r * 1024 + c;
                w[widx] = fp8b(s[0] * 64.f) | (fp8b(s[1] * 64.f) << 8)
                        | (fp8b(s[2] * 64.f) << 16) | (fp8b(s[3] * 64.f) << 24);
            }
            uint4 v;
            v.x = w[0]; v.y = w[1]; v.z = w[2]; v.w = w[3];
            g_W8[i] = v;
        }
        else if (i < S1) {
            int r = i - S0;
            int lane = r & 31;
            int t2 = r >> 5;
            int kc = t2 & 127;
            int mt = t2 >> 7;
            int r0 = mt * 16 + (lane >> 2);
            int c0 = kc * 16 + (lane & 3) * 2;
            uint4 v;
            v.x = pk2(wg_src(Wihd, Whhd, r0, c0), wg_src(Wihd, Whhd, r0, c0 + 1));
            v.y = pk2(wg_src(Wihd, Whhd, r0 + 8, c0), wg_src(Wihd, Whhd, r0 + 8, c0 + 1));
            v.z = pk2(wg_src(Wihd, Whhd, r0, c0 + 8), wg_src(Wihd, Whhd, r0, c0 + 9));
            v.w = pk2(wg_src(Wihd, Whhd, r0 + 8, c0 + 8), wg_src(Wihd, Whhd, r0 + 8, c0 + 9));
            g_WgP[r] = v;
        }
        else if (i < S2) pack_one(g_WcP, Wc, i - S1, 7, 2048);
        else if (i < S3) pack_one(g_WihfP, Wihf, i - S2, 5, 512);
        else if (i < S4) pack_one(g_WihbP, Wihb, i - S3, 5, 512);
        else pack_one(g_WattnP, Wattn, i - S4, 7, 2048);
    }
}

// ---------------- misc conversion + init ----------------
__global__ void conv_misc(const float* __restrict__ Whhf, const float* __restrict__ Whhb,
                          const float* __restrict__ emb_enc, const int* __restrict__ x,
                          const float* __restrict__ bihd, const float* __restrict__ bhhd) {
    const int A0 = 1048576, A1 = 2097152, A2 = 2162688, A3 = 2166784, A4 = 2199552;
    for (int i = blockIdx.x * blockDim.x + threadIdx.x; i < A4; i += gridDim.x * blockDim.x) {
        if (i < A0) g_Whhf_bf[i] = __float2bfloat16(Whhf[i]);
        else if (i < A1) g_Whhb_bf[i - A0] = __float2bfloat16(Whhb[i - A0]);
        else if (i < A2) {
            int r = i - A1;
            int tt = r >> 9, k = r & 511;
            g_E0_bf[r] = __float2bfloat16(emb_enc[(size_t)x[tt] * 512 + k]);
        } else if (i < A3) {
            int r = i - A2;
            int srow = (r & 3) * 1024 + (r >> 2);
            g_bg[r] = bihd[srow] + bhhd[srow];
        } else {
            int r = i - A3;
            g_c[r] = 0.f;
            int b = r >> 10, j = r & 1023;
            g_xattn[b * 2048 + 1024 + j] = __float2bfloat16(0.f);
            if (r < 2048) ((float*)g_henc)[r] = 0.f;
            if (r < 1024) ((float*)g_cenc)[r] = 0.f;
        }
    }
}

// ---------------- packed-A GEMM (encoder precompute) ------
template <int KC, int NT>
__global__ __launch_bounds__(128) void gemm_packed(
    const uint4* __restrict__ Ap, const __nv_bfloat16* __restrict__ X, int xld,
    const float* __restrict__ bias, const float* __restrict__ bias2,
    float* __restrict__ outF, int ofld)
{
    int w = (blockIdx.x * blockDim.x + threadIdx.x) >> 5;
    int lane = threadIdx.x & 31;
    int gr = lane >> 2;
    int gc = (lane & 3) * 2;
    float acc[NT][4];
#pragma unroll
    for (int a = 0; a < NT; a++)
#pragma unroll
        for (int q = 0; q < 4; q++) acc[a][q] = 0.f;

    const uint4* ap = Ap + (size_t)w * KC * 32 + lane;
#pragma unroll 8
    for (int kc = 0; kc < KC; kc++) {
        uint4 a = ap[(size_t)kc * 32];
#pragma unroll
        for (int nt = 0; nt < NT; nt++) {
            const __nv_bfloat16* xb = X + (size_t)(nt * 8 + gr) * xld + gc + kc * 16;
            unsigned b0 = *(const unsigned*)xb;
            unsigned b1 = *(const unsigned*)(xb + 8);
            MMA_BF16(acc[nt], a, b0, b1);
        }
    }
    int mA = w * 16 + gr, mB = mA + 8;
    float bA = bias[mA] + bias2[mA];
    float bB = bias[mB] + bias2[mB];
#pragma unroll
    for (int nt = 0; nt < NT; nt++) {
        int n0 = nt * 8 + gc;
        outF[(size_t)n0 * ofld + mA] = acc[nt][0] + bA;
        outF[(size_t)(n0 + 1) * ofld + mA] = acc[nt][1] + bA;
        outF[(size_t)n0 * ofld + mB] = acc[nt][2] + bB;
        outF[(size_t)(n0 + 1) * ofld + mB] = acc[nt][3] + bB;
    }
}

// ---------------- persistent encoder ----------------
__global__ __launch_bounds__(256) void enc_persist() {
    __shared__ float sg[32];
    int dir = blockIdx.x >> 6, jb = blockIdx.x & 63, tid = threadIdx.x;
    int rl = tid >> 3, part = tid & 7;
    int q = rl >> 3, jl = rl & 7;
    int row = q * 512 + jb * 8 + jl;
    const uint4* Wr = (const uint4*)((dir ? g_Whhb_bf : g_Whhf_bf) + (size_t)row * 512 + part * 64);
    const float* Xr = dir ? g_Xb : g_Xf;
    for (int t = 0; t < 128; t++) {
        const float4* hp = (const float4*)(g_henc[t & 1][dir] + part * 64);
        float acc = 0.f;
#pragma unroll
        for (int k = 0; k < 8; k++) {
            float4 h0 = __ldcg(hp + 2 * k);
            float4 h1 = __ldcg(hp + 2 * k + 1);
            acc += dot8f(Wr[k], h0, h1);
        }
        acc += __shfl_xor_sync(0xffffffffu, acc, 1);
        acc += __shfl_xor_sync(0xffffffffu, acc, 2);
        acc += __shfl_xor_sync(0xffffffffu, acc, 4);
        if (part == 0) sg[rl] = acc + Xr[t * 2048 + row];
        __syncthreads();
        if (tid < 8) {
            int j = jb * 8 + tid;
            float iv = sg[tid], fv = sg[8 + tid], gv = sg[16 + tid], ov = sg[24 + tid];
            float c = g_cenc[dir][j];
            c = sigm(fv) * c + sigm(iv) * tanhf(gv);
            float h = sigm(ov) * tanhf(c);
            g_cenc[dir][j] = c;
            g_henc[(t + 1) & 1][dir][j] = h;
            g_EOm[t * 1024 + dir * 512 + j] = __float2bfloat16(h);
        }
        __syncthreads();
        if (tid == 0) {
            __threadfence();
            unsigned long long old = atomicAdd(&g_ectr, 1ull);
            unsigned long long tv = ((old >> 7) << 7) + 128ull;
            unsigned long long v;
            do {
                asm volatile("ld.global.cg.u64 %0, [%1];" : "=l"(v) : "l"(&g_ectr));
            } while (v < tv);
            __threadfence();
        }
        __syncthreads();
    }
}

// ---------------- M = Wc_ctx @ EO^T  (1024 x 128, one-time) -----------------
__global__ __launch_bounds__(128) void gemm_M() {
    __shared__ float part[4][16][129];
    int wl = threadIdx.x >> 5, lane = threadIdx.x & 31;
    int gr = lane >> 2, gc = (lane & 3) * 2;
    int tile = blockIdx.x;
    float acc[16][4];
#pragma unroll
    for (int a = 0; a < 16; a++)
#pragma unroll
        for (int q = 0; q < 4; q++) acc[a][q] = 0.f;
    int kc0 = 64 + wl * 16;
#pragma unroll 4
    for (int kk = 0; kk < 16; kk++) {
        int kc = kc0 + kk;
        uint4 a = g_WcP[(size_t)tile * 4096 + kc * 32 + lane];
        int d0 = (kc - 64) * 16 + gc;
#pragma unroll
        for (int nt = 0; nt < 16; nt++) {
            unsigned b0 = *(const unsigned*)(g_EOm + (size_t)(nt * 8 + gr) * 1024 + d0);
            unsigned b1 = *(const unsigned*)(g_EOm + (size_t)(nt * 8 + gr) * 1024 + d0 + 8);
            MMA_BF16(acc[nt], a, b0, b1);
        }
    }
#pragma unroll
    for (int nt = 0; nt < 16; nt++) {
        int n0 = nt * 8 + gc;
        part[wl][gr][n0] = acc[nt][0];
        part[wl][gr][n0 + 1] = acc[nt][1];
        part[wl][gr + 8][n0] = acc[nt][2];
        part[wl][gr + 8][n0 + 1] = acc[nt][3];
    }
    __syncthreads();
    for (int it = 0; it < 16; it++) {
        int idx = threadIdx.x + it * 128;
        int rr = idx >> 7, l = idx & 127;
        g_Mf[(size_t)(tile * 16 + rr) * 128 + l] =
            part[0][rr][l] + part[1][rr][l] + part[2][rr][l] + part[3][rr][l];
    }
}

__global__ void pack_M() {
    int i = blockIdx.x * 256 + threadIdx.x;   // 16384
    pack_one(g_MP, g_Mf, i, 3, 128);
}

// ---------------- persistent decoder ----------------
__device__ __forceinline__ void gbar() {
    __syncthreads();
    if (threadIdx.x == 0) {
        __threadfence();
        unsigned long long old = atomicAdd(&g_dctr, 1ull);
        unsigned long long tv = (old / G) * G + G;
        unsigned long long v;
        do {
            asm volatile("ld.global.cg.u64 %0, [%1];" : "=l"(v) : "l"(&g_dctr));
        } while (v < tv);
        __threadfence();
    }
    __syncthreads();
}

__global__ __launch_bounds__(256) void dec_persist(
    const float* __restrict__ emb_dec, const float* __restrict__ battn,
    const float* __restrict__ bcomb, const float* __restrict__ bout,
    const int* __restrict__ tgt)
{
    extern __shared__ __align__(16) char dsm[];
    int bid = blockIdx.x, tid = threadIdx.x;
    int wl = tid >> 5, lane = tid & 31;
    int gr = lane >> 2, gc = (lane & 3) * 2, tc = lane & 3;

    for (int t = 0; t <= 128; t++) {
        // ======== P1: token resolve + embed (blocks 0..31) ========
        if (bid < 32) {
            int b = bid;
            int tok = SOSTOK;
            if (t > 0) {
                unsigned long long* rk = (unsigned long long*)dsm;
                float* rs = (float*)(dsm + 1024);
                unsigned long long k = 0;
                float s = 0.f;
                if (tid < G) {
                    k = __ldcg(&g_amaxP[tid * 32 + b]);
                    s = __ldcg(&g_sumP[tid * 32 + b]);
                }
                if (tid < 128) { rk[tid] = k; rs[tid] = s; }
                __syncthreads();
                for (int off = 64; off; off >>= 1) {
                    if (tid < off) {
                        if (rk[tid + off] > rk[tid]) rk[tid] = rk[tid + off];
                        rs[tid] += rs[tid + off];
                    }
                    __syncthreads();
                }
                tok = (int)(0xFFFFFFFFu - (unsigned)(rk[0] & 0xFFFFFFFFull));
                if (tid == 0) {
                    float lse = logf(rs[0]);
                    float tl = __ldcg(&g_tgtL[b]);
                    g_nll[(t - 1) * 32 + b] = -(tl - lse);
                }
            }
            if (t < 128) {
                const float4* er = (const float4*)(emb_dec + (size_t)tok * 1024);
                float4 v = er[tid];
                unsigned* xa = (unsigned*)(g_xattn + b * 2048 + tid * 4);
                xa[0] = pk2(v.x, v.y);
                xa[1] = pk2(v.z, v.w);
            }
        }
        gbar();
        if (t == 128) break;

        // ======== P2: comb_e (0..63) | scores (64..71) | gates_h (72..103) ==
        if (bid < 64) {
            __nv_bfloat16 (*sx)[520] = (__nv_bfloat16 (*)[520])dsm;
            float (*part)[16][33] = (float (*)[16][33])dsm;
            float acc[4][4];
#pragma unroll
            for (int a = 0; a < 4; a++)
#pragma unroll
                for (int q2 = 0; q2 < 4; q2++) acc[a][q2] = 0.f;
            for (int ch = 0; ch < 2; ch++) {
                __syncthreads();
                for (int i = tid; i < 2048; i += 256) {
                    int r = i >> 6, c = i & 63;
                    *(uint4*)&sx[r][c * 8] =
                        __ldcg((const uint4*)(g_xattn + (size_t)r * 2048 + ch * 512 + c * 8));
                }
                __syncthreads();
#pragma unroll
                for (int kk = 0; kk < 4; kk++) {
                    int kcl = wl * 4 + kk;
                    int kc = ch * 32 + kcl;
                    uint4 a = g_WcP[(size_t)bid * 4096 + kc * 32 + lane];
#pragma unroll
                    for (int nt = 0; nt < 4; nt++) {
                        unsigned b0 = *(const unsigned*)&sx[nt * 8 + gr][kcl * 16 + gc];
                        unsigned b1 = *(const unsigned*)&sx[nt * 8 + gr][kcl * 16 + gc + 8];
                        MMA_BF16(acc[nt], a, b0, b1);
                    }
                }
            }
            __syncthreads();
#pragma unroll
            for (int nt = 0; nt < 4; nt++) {
                int n0 = nt * 8 + gc;
                part[wl][gr][n0] = acc[nt][0];
                part[wl][gr][n0 + 1] = acc[nt][1];
                part[wl][gr + 8][n0] = acc[nt][2];
                part[wl][gr + 8][n0 + 1] = acc[nt][3];
            }
            __syncthreads();
#pragma unroll
            for (int it = 0; it < 2; it++) {
                int idx = tid + it * 256;
                int rr = idx >> 5, b = idx & 31;
                float s = 0.f;
#pragma unroll
                for (int w2 = 0; w2 < 8; w2++) s += part[w2][rr][b];
                g_cE[(bid * 16 + rr) * 32 + b] = s;
            }
        } else if (bid < 72) {
            int tile = bid - 64;
            __nv_bfloat16 (*sx)[520] = (__nv_bfloat16 (*)[520])dsm;
            float (*part)[16][33] = (float (*)[16][33])dsm;
            float acc[4][4];
#pragma unroll
            for (int a = 0; a < 4; a++)
#pragma unroll
                for (int q2 = 0; q2 < 4; q2++) acc[a][q2] = 0.f;
            for (int ch = 0; ch < 4; ch++) {
                __syncthreads();
                for (int i = tid; i < 2048; i += 256) {
                    int r = i >> 6, c = i & 63;
                    *(uint4*)&sx[r][c * 8] =
                        __ldcg((const uint4*)(g_xattn + (size_t)r * 2048 + ch * 512 + c * 8));
                }
                __syncthreads();
#pragma unroll
                for (int kk = 0; kk < 4; kk++) {
                    int kcl = wl * 4 + kk;
                    int kc = ch * 32 + kcl;
                    uint4 a = g_WattnP[(size_t)tile * 4096 + kc * 32 + lane];
#pragma unroll
                    for (int nt = 0; nt < 4; nt++) {
                        unsigned b0 = *(const unsigned*)&sx[nt * 8 + gr][kcl * 16 + gc];
                        unsigned b1 = *(const unsigned*)&sx[nt * 8 + gr][kcl * 16 + gc + 8];
                        MMA_BF16(acc[nt], a, b0, b1);
                    }
                }
            }
            __syncthreads();
#pragma unroll
            for (int nt = 0; nt < 4; nt++) {
                int n0 = nt * 8 + gc;
                part[wl][gr][n0] = acc[nt][0];
                part[wl][gr][n0 + 1] = acc[nt][1];
                part[wl][gr + 8][n0] = acc[nt][2];
                part[wl][gr + 8][n0 + 1] = acc[nt][3];
            }
            __syncthreads();
#pragma unroll
            for (int it = 0; it < 2; it++) {
                int idx = tid + it * 256;
                int rr = idx >> 5, b = idx & 31;
                float s = battn[tile * 16 + rr];
#pragma unroll
                for (int w2 = 0; w2 < 8; w2++) s += part[w2][rr][b];
                g_sc[(tile * 16 + rr) * 32 + b] = s;
            }
        } else if (bid < 104) {
            int gb = bid - 72;
            __nv_bfloat16 (*sx)[520] = (__nv_bfloat16 (*)[520])dsm;
            int tile = gb * 8 + wl;
            float acc[4][4];
#pragma unroll
            for (int a = 0; a < 4; a++)
#pragma unroll
                for (int q2 = 0; q2 < 4; q2++) acc[a][q2] = 0.f;
            for (int ch = 0; ch < 2; ch++) {
                __syncthreads();
                for (int i = tid; i < 2048; i += 256) {
                    int r = i >> 6, c = i & 63;
                    *(uint4*)&sx[r][c * 8] =
                        __ldcg((const uint4*)(g_xattn + (size_t)r * 2048 + 1024 + ch * 512 + c * 8));
                }
                __syncthreads();
#pragma unroll 8
                for (int kk = 0; kk < 32; kk++) {
                    int kc = 64 + ch * 32 + kk;
                    uint4 a = g_WgP[(size_t)tile * 4096 + kc * 32 + lane];
#pragma unroll
                    for (int nt = 0; nt < 4; nt++) {
                        unsigned b0 = *(const unsigned*)&sx[nt * 8 + gr][kk * 16 + gc];
                        unsigned b1 = *(const unsigned*)&sx[nt * 8 + gr][kk * 16 + gc + 8];
                        MMA_BF16(acc[nt], a, b0, b1);
                    }
                }
            }
            int rA = tile * 16 + gr, rB = rA + 8;
#pragma unroll
            for (int nt = 0; nt < 4; nt++) {
                int n0 = nt * 8 + gc;
                g_gh[(size_t)rA * 32 + n0] = acc[nt][0];
                g_gh[(size_t)rA * 32 + n0 + 1] = acc[nt][1];
                g_gh[(size_t)rB * 32 + n0] = acc[nt][2];
                g_gh[(size_t)rB * 32 + n0 + 1] = acc[nt][3];
            }
        }
        gbar();

        // ======== P3: softmax + M@aw + finalize comb (blocks 0..31) ========
        if (bid < 32) {
            __nv_bfloat16 (*saw)[136] = (__nv_bfloat16 (*)[136])dsm;
            float (*part3)[4][16][33] = (float (*)[4][16][33])(dsm + 16384);
#pragma unroll
            for (int i = 0; i < 4; i++) {
                int b = wl * 4 + i;
                float v0 = __ldcg(&g_sc[lane * 32 + b]);
                float v1 = __ldcg(&g_sc[(lane + 32) * 32 + b]);
                float v2 = __ldcg(&g_sc[(lane + 64) * 32 + b]);
                float v3 = __ldcg(&g_sc[(lane + 96) * 32 + b]);
                float mx = fmaxf(fmaxf(v0, v1), fmaxf(v2, v3));
#pragma unroll
                for (int o = 16; o; o >>= 1) mx = fmaxf(mx, __shfl_xor_sync(0xffffffffu, mx, o));
                float e0 = expf(v0 - mx), e1 = expf(v1 - mx), e2 = expf(v2 - mx), e3 = expf(v3 - mx);
                float s = e0 + e1 + e2 + e3;
#pragma unroll
                for (int o = 16; o; o >>= 1) s += __shfl_xor_sync(0xffffffffu, s, o);
                float inv = 1.f / s;
                saw[b][lane] = __float2bfloat16(e0 * inv);
                saw[b][lane + 32] = __float2bfloat16(e1 * inv);
                saw[b][lane + 64] = __float2bfloat16(e2 * inv);
                saw[b][lane + 96] = __float2bfloat16(e3 * inv);
            }
            __syncthreads();
            {
                int tt = wl >> 2, q4 = wl & 3;
                int tile = bid * 2 + tt;
                float acc[4][4];
#pragma unroll
                for (int a = 0; a < 4; a++)
#pragma unroll
                    for (int q2 = 0; q2 < 4; q2++) acc[a][q2] = 0.f;
#pragma unroll
                for (int kk = 0; kk < 2; kk++) {
                    int kc = q4 * 2 + kk;
                    uint4 a = g_MP[((size_t)tile * 8 + kc) * 32 + lane];
#pragma unroll
                    for (int nt = 0; nt < 4; nt++) {
                        unsigned b0 = *(const unsigned*)&saw[nt * 8 + gr][kc * 16 + gc];
                        unsigned b1 = *(const unsigned*)&saw[nt * 8 + gr][kc * 16 + gc + 8];
                        MMA_BF16(acc[nt], a, b0, b1);
                    }
                }
#pragma unroll
                for (int nt = 0; nt < 4; nt++) {
                    int n0 = nt * 8 + gc;
                    part3[tt][q4][gr][n0] = acc[nt][0];
                    part3[tt][q4][gr][n0 + 1] = acc[nt][1];
                    part3[tt][q4][gr + 8][n0] = acc[nt][2];
                    part3[tt][q4][gr + 8][n0 + 1] = acc[nt][3];
                }
            }
            __syncthreads();
#pragma unroll
            for (int it = 0; it < 4; it++) {
                int idx = tid + it * 256;
                int rr2 = idx >> 5, b = idx & 31;
                int tt2 = rr2 >> 4, rr = rr2 & 15;
                int row = bid * 32 + rr2;
                float s = __ldcg(&g_cE[row * 32 + b]) + bcomb[row];
#pragma unroll
                for (int q2 = 0; q2 < 4; q2++) s += part3[tt2][q2][rr][b];
                g_comb[b * 1024 + row] = __float2bfloat16(fmaxf(s, 0.f));
            }
        }
        gbar();

        // ======== P4: gates_comb + gh + cell (blocks 0..63) ========
        if (bid < 64) {
            __nv_bfloat16 (*sx)[520] = (__nv_bfloat16 (*)[520])dsm;
            float (*part)[2][16][33] = (float (*)[2][16][33])dsm;
            int tl = wl >> 1, half = wl & 1;
            int tile = bid * 4 + tl;
            float acc[4][4];
#pragma unroll
            for (int a = 0; a < 4; a++)
#pragma unroll
                for (int q2 = 0; q2 < 4; q2++) acc[a][q2] = 0.f;
            for (int ch = 0; ch < 2; ch++) {
                __syncthreads();
                for (int i = tid; i < 2048; i += 256) {
                    int r = i >> 6, c = i & 63;
                    *(uint4*)&sx[r][c * 8] =
                        __ldcg((const uint4*)(g_comb + (size_t)r * 1024 + ch * 512 + c * 8));
                }
                __syncthreads();
#pragma unroll
                for (int kk = 0; kk < 16; kk++) {
                    int kcl = half * 16 + kk;
                    int kc = ch * 32 + kcl;
                    uint4 a = g_WgP[(size_t)tile * 4096 + kc * 32 + lane];
#pragma unroll
                    for (int nt = 0; nt < 4; nt++) {
                        unsigned b0 = *(const unsigned*)&sx[nt * 8 + gr][kcl * 16 + gc];
                        unsigned b1 = *(const unsigned*)&sx[nt * 8 + gr][kcl * 16 + gc + 8];
                        MMA_BF16(acc[nt], a, b0, b1);
                    }
                }
            }
            __syncthreads();
#pragma unroll
            for (int nt = 0; nt < 4; nt++) {
                int n0 = nt * 8 + gc;
                part[tl][half][gr][n0] = acc[nt][0];
                part[tl][half][gr][n0 + 1] = acc[nt][1];
                part[tl][half][gr + 8][n0] = acc[nt][2];
                part[tl][half][gr + 8][n0 + 1] = acc[nt][3];
            }
            __syncthreads();
#pragma unroll
            for (int it = 0; it < 2; it++) {
                int idx = tid + it * 256;
                int jl = idx >> 5, b = idx & 31;
                float gt[4];
#pragma unroll
                for (int q2 = 0; q2 < 4; q2++) {
                    int lr = jl * 4 + q2;
                    int grow = bid * 64 + lr;
                    gt[q2] = part[lr >> 4][0][lr & 15][b] + part[lr >> 4][1][lr & 15][b]
                           + g_bg[grow] + __ldcg(&g_gh[(size_t)grow * 32 + b]);
                }
                int jg = bid * 16 + jl;
                float c = g_c[b * 1024 + jg];
                c = sigm(gt[1]) * c + sigm(gt[0]) * tanhf(gt[2]);
                float h = sigm(gt[3]) * tanhf(c);
                g_c[b * 1024 + jg] = c;
                g_xattn[b * 2048 + 1024 + jg] = __float2bfloat16(h);
                g_h8[b * 1024 + jg] = (unsigned char)fp8b(h * 256.f);
            }
        }
        gbar();

        // ======== P5: fp8 logits + partials (all 125 blocks) ========
        {
            unsigned char (*sx8)[1040] = (unsigned char (*)[1040])dsm;
            int tile0 = (bid * 8 + wl) * 2;
            for (int i = tid; i < 2048; i += 256) {
                int r = i >> 6, c2 = i & 63;
                *(uint4*)&sx8[r][c2 * 16] = __ldcg((const uint4*)(g_h8 + r * 1024 + c2 * 16));
            }
            __syncthreads();
            float acc[2][4][4];
#pragma unroll
            for (int m = 0; m < 2; m++)
#pragma unroll
                for (int a = 0; a < 4; a++)
#pragma unroll
                    for (int q2 = 0; q2 < 4; q2++) acc[m][a][q2] = 0.f;
#pragma unroll 4
            for (int kc = 0; kc < 32; kc++) {
                uint4 a0 = g_W8[((size_t)tile0 * 32 + kc) * 32 + lane];
                uint4 a1 = g_W8[((size_t)(tile0 + 1) * 32 + kc) * 32 + lane];
#pragma unroll
                for (int nt = 0; nt < 4; nt++) {
                    unsigned b0 = *(const unsigned*)&sx8[nt * 8 + gr][kc * 32 + 4 * tc];
                    unsigned b1 = *(const unsigned*)&sx8[nt * 8 + gr][kc * 32 + 4 * tc + 16];
                    MMA_FP8(acc[0][nt], a0, b0, b1);
                    MMA_FP8(acc[1][nt], a1, b0, b1);
                }
            }
            __syncthreads();
            float* sL = (float*)dsm;
            const float sc8 = 1.f / 16384.f;
#pragma unroll
            for (int m = 0; m < 2; m++) {
                int rA = (wl * 2 + m) * 16 + gr, rB = rA + 8;
                float bA = bout[bid * 256 + rA], bB = bout[bid * 256 + rB];
#pragma unroll
                for (int nt = 0; nt < 4; nt++) {
                    int n0 = nt * 8 + gc;
                    sL[rA * 33 + n0] = acc[m][nt][0] * sc8 + bA;
                    sL[rA * 33 + n0 + 1] = acc[m][nt][1] * sc8 + bA;
                    sL[rB * 33 + n0] = acc[m][nt][2] * sc8 + bB;
                    sL[rB * 33 + n0 + 1] = acc[m][nt][3] * sc8 + bB;
                }
            }
            __syncthreads();
            unsigned long long* pkey = (unsigned long long*)(dsm + 34816);
            float* psum = (float*)(dsm + 36864);
            int b2 = tid & 31, seg = tid >> 5;
            unsigned long long bk = 0;
            float sm = 0.f;
#pragma unroll 4
            for (int r0 = 0; r0 < 32; r0++) {
                int r = seg * 32 + r0;
                float f = sL[r * 33 + b2];
                unsigned long long key = ((unsigned long long)fordu(f) << 32)
                                       | (unsigned long long)(0xFFFFFFFFu - (unsigned)(bid * 256 + r));
                if (key > bk) bk = key;
                sm += expf(f);
            }
            pkey[tid] = bk;
            psum[tid] = sm;
            __syncthreads();
            if (seg == 0) {
#pragma unroll
                for (int s2 = 1; s2 < 8; s2++) {
                    unsigned long long k2 = pkey[s2 * 32 + b2];
                    if (k2 > bk) bk = k2;
                    sm += psum[s2 * 32 + b2];
                }
                g_amaxP[bid * 32 + b2] = bk;
                g_sumP[bid * 32 + b2] = sm;
            }
            if (tid < 32) {
                int tr = tgt[tid * 128 + t];
                if ((tr >> 8) == bid) g_tgtL[tid] = sL[(tr & 255) * 33 + tid];
            }
        }
        gbar();
    }
}

__global__ void finalize_kernel(float* __restrict__ out) {
    int b = threadIdx.x;  // 32
    float s = 0.f;
    for (int t = 0; t < 128; t++) s += g_nll[t * 32 + b];
    for (int o = 16; o > 0; o >>= 1) s += __shfl_down_sync(0xffffffffu, s, o);
    if (b == 0) {
        float loss = s / 32.0f;
        out[0] = loss;
        out[1] = loss / 128.0f;
    }
}

// ---------------- host launcher ----------------
extern "C" void kernel_launch(void* const* d_in, const int* in_sizes, int n_in,
                              void* d_out, int out_size) {
    const int* x = (const int*)d_in[0];
    const int* tgt = (const int*)d_in[1];
    const float* emb_enc = (const float*)d_in[4];
    const float* Wihf = (const float*)d_in[5];
    const float* Whhf = (const float*)d_in[6];
    const float* bihf = (const float*)d_in[7];
    const float* bhhf = (const float*)d_in[8];
    const float* Wihb = (const float*)d_in[9];
    const float* Whhb = (const float*)d_in[10];
    const float* bihb = (const float*)d_in[11];
    const float* bhhb = (const float*)d_in[12];
    const float* emb_dec = (const float*)d_in[13];
    const float* Wattn = (const float*)d_in[14];
    const float* battn = (const float*)d_in[15];
    const float* Wc = (const float*)d_in[16];
    const float* bcomb = (const float*)d_in[17];
    const float* Wihd = (const float*)d_in[18];
    const float* Whhd = (const float*)d_in[19];
    const float* bihd = (const float*)d_in[20];
    const float* bhhd = (const float*)d_in[21];
    const float* Wout = (const float*)d_in[22];
    const float* bout = (const float*)d_in[23];

    uint4 *pWihfP, *pWihbP;
    __nv_bfloat16* pE0;
    float *pXf, *pXb;
    cudaGetSymbolAddress((void**)&pWihfP, g_WihfP);
    cudaGetSymbolAddress((void**)&pWihbP, g_WihbP);
    cudaGetSymbolAddress((void**)&pE0, g_E0_bf);
    cudaGetSymbolAddress((void**)&pXf, g_Xf);
    cudaGetSymbolAddress((void**)&pXb, g_Xb);

    cudaFuncSetAttribute(dec_persist, cudaFuncAttributeMaxDynamicSharedMemorySize, 59392);

    pack_all<<<2048, 256>>>(Wout, Wihd, Whhd, Wc, Wihf, Wihb, Wattn);
    conv_misc<<<1024, 256>>>(Whhf, Whhb, emb_enc, x, bihd, bhhd);
    gemm_packed<32, 16><<<32, 128>>>(pWihfP, pE0, 512, bihf, bhhf, pXf, 2048);
    gemm_packed<32, 16><<<32, 128>>>(pWihbP, pE0, 512, bihb, bhhb, pXb, 2048);
    enc_persist<<<128, 256>>>();
    gemm_M<<<64, 128>>>();
    pack_M<<<64, 256>>>();
    dec_persist<<<G, 256, 59392>>>(emb_dec, battn, bcomb, bout, tgt);
    finalize_kernel<<<1, 32>>>((float*)d_out);
}